// round 4
// baseline (speedup 1.0000x reference)
#include <cuda_runtime.h>
#include <cstdint>

// Problem shape (fixed by the dataset):
//   input    f32 [B=4, C=64, H=512, W=512]
//   gathered f32 [N=2048, C=64, kh=16, kw=16]
//   indices  (b, h_block, w_block) per row; dtype int32 or int64, detected
//            on device.
//
// stride == kernel == 16 -> patches tile the image into 4096 disjoint 16x16
// slots; only duplicate indices overlap. Build per-slot linked lists of patch
// ids (atomicExch, tiny single-block kernel), then one streaming pass:
//   out = in + sum(patches in this element's slot)
// Traffic ~= 256MB (in) + 128MB (gathered) + 256MB (out) = 640MB, no atomics
// on the hot path, float4-coalesced, 4x ILP per thread for latency hiding.

#define BB 4
#define CC 64
#define HH 512
#define WW 512
#define NN 2048
#define NSLOTS 4096   // BB * (HH/16) * (WW/16)
#define UNROLL 4

__device__ int g_head[NSLOTS];
__device__ int g_next[NN];

// Single-block setup: init heads, detect index dtype, build per-slot lists.
// Dtype detection: read first 3072 uint64 words = 24576 bytes (= full buffer
// if int32 (N*3*4), half if int64 (N*3*8) -- safe either way). True int64
// indices are all < 512 so the high 32 bits are always 0; int32 data read as
// int64 packs the neighboring field into the high word (nonzero somewhere
// with overwhelming probability over 3072 words).
__global__ void __launch_bounds__(1024) setup_kernel(const void* __restrict__ idx_raw) {
    __shared__ int s_is64;
    int t = threadIdx.x;
    if (t == 0) s_is64 = 1;
    #pragma unroll
    for (int i = t; i < NSLOTS; i += 1024) g_head[i] = -1;
    __syncthreads();

    const unsigned long long* w = (const unsigned long long*)idx_raw;
    #pragma unroll
    for (int i = t; i < 3072; i += 1024)
        if ((w[i] >> 32) != 0ull) s_is64 = 0;
    __syncthreads();

    bool is64 = (s_is64 != 0);
    #pragma unroll
    for (int n = t; n < NN; n += 1024) {
        int b, hb, wb;
        if (is64) {
            const long long* idx = (const long long*)idx_raw;
            b  = (int)idx[3 * n + 0];
            hb = (int)idx[3 * n + 1];
            wb = (int)idx[3 * n + 2];
        } else {
            const int* idx = (const int*)idx_raw;
            b  = idx[3 * n + 0];
            hb = idx[3 * n + 1];
            wb = idx[3 * n + 2];
        }
        int slot = (b << 10) | (hb << 5) | wb;
        g_next[n] = atomicExch(&g_head[slot & (NSLOTS - 1)], n);
    }
}

// 4 float4 per thread, stride 256 inside a 1024-float4 block tile.
// 16,777,216 float4 total -> 16384 blocks of 256 threads.
__global__ void __launch_bounds__(256) scatter_main_kernel(
    const float4* __restrict__ in4,
    const float4* __restrict__ g4,
    float4* __restrict__ out4)
{
    unsigned base = blockIdx.x * (256u * UNROLL) + threadIdx.x;

    float4   val[UNROLL];
    int      p[UNROLL];
    unsigned local[UNROLL];

    #pragma unroll
    for (int k = 0; k < UNROLL; k++) {
        unsigned i4 = base + k * 256u;
        unsigned w4 = i4 & 127u;           // float4 column: w = w4*4
        unsigned h  = (i4 >> 7) & 511u;
        unsigned c  = (i4 >> 16) & 63u;
        unsigned b  = i4 >> 22;
        unsigned slot = (b << 10) | ((h >> 4) << 5) | (w4 >> 2);
        p[k]     = g_head[slot];
        local[k] = (c << 6) | ((h & 15u) << 2) | (w4 & 3u);
        val[k]   = in4[i4];
    }

    #pragma unroll
    for (int k = 0; k < UNROLL; k++) {
        int q = p[k];
        while (q >= 0) {
            float4 g = g4[((unsigned)q << 12) + local[k]];
            val[k].x += g.x; val[k].y += g.y;
            val[k].z += g.z; val[k].w += g.w;
            q = g_next[q];
        }
    }

    #pragma unroll
    for (int k = 0; k < UNROLL; k++)
        out4[base + k * 256u] = val[k];
}

extern "C" void kernel_launch(void* const* d_in, const int* in_sizes, int n_in,
                              void* d_out, int out_size) {
    const float* input    = (const float*)d_in[0];
    const float* gathered = (const float*)d_in[1];
    const void*  indices  = d_in[2];
    float* out = (float*)d_out;

    setup_kernel<<<1, 1024>>>(indices);

    const unsigned total4 = (unsigned)(BB * CC * HH * WW) / 4u;  // 16,777,216
    scatter_main_kernel<<<total4 / (256u * UNROLL), 256>>>(
        (const float4*)input, (const float4*)gathered, (float4*)out);
}

// round 5
// speedup vs baseline: 1.2057x; 1.2057x over previous
#include <cuda_runtime.h>
#include <cstdint>

// input f32 [4,64,512,512], gathered f32 [2048,64,16,16], indices (b,hb,wb)
// int32 or int64 (detected on device). stride==kernel==16 -> 4096 disjoint
// 16x16 slots; duplicates handled via per-slot linked lists. Main pass:
// out = in + sum(patches in slot), 640MB total traffic, 256-bit accesses.

#define BB 4
#define CC 64
#define HH 512
#define WW 512
#define NN 2048
#define NSLOTS 4096   // BB * 32 * 32

__device__ int g_head[NSLOTS];
__device__ int g_next[NN];

__global__ void __launch_bounds__(256) init_heads_kernel() {
    int i = blockIdx.x * 256 + threadIdx.x;
    if (i < NSLOTS) g_head[i] = -1;
}

// 8 blocks x 256 threads. Each block independently detects the index dtype
// (scanning the first 3072 uint64 words = 24576 bytes, safe for either
// dtype: full buffer if int32, half if int64; genuine int64 index values are
// < 512 so high words are all zero), then builds its slice of the lists.
__global__ void __launch_bounds__(256) build_lists_kernel(const void* __restrict__ idx_raw) {
    __shared__ int s_is64;
    int t = threadIdx.x;
    if (t == 0) s_is64 = 1;
    __syncthreads();
    const unsigned long long* w = (const unsigned long long*)idx_raw;
    #pragma unroll
    for (int i = t; i < 3072; i += 256)
        if ((w[i] >> 32) != 0ull) s_is64 = 0;   // benign race
    __syncthreads();

    int n = blockIdx.x * 256 + t;               // < NN
    int b, hb, wb;
    if (s_is64) {
        const long long* idx = (const long long*)idx_raw;
        b  = (int)idx[3 * n + 0];
        hb = (int)idx[3 * n + 1];
        wb = (int)idx[3 * n + 2];
    } else {
        const int* idx = (const int*)idx_raw;
        b  = idx[3 * n + 0];
        hb = idx[3 * n + 1];
        wb = idx[3 * n + 2];
    }
    int slot = (b << 10) | (hb << 5) | wb;
    g_next[n] = atomicExch(&g_head[slot & (NSLOTS - 1)], n);
}

__device__ __forceinline__ void ldg256(const float* p, float* v) {
    asm volatile("ld.global.v8.f32 {%0,%1,%2,%3,%4,%5,%6,%7}, [%8];"
                 : "=f"(v[0]), "=f"(v[1]), "=f"(v[2]), "=f"(v[3]),
                   "=f"(v[4]), "=f"(v[5]), "=f"(v[6]), "=f"(v[7])
                 : "l"(p));
}

__device__ __forceinline__ void stg256(float* p, const float* v) {
    asm volatile("st.global.v8.f32 [%0], {%1,%2,%3,%4,%5,%6,%7,%8};"
                 :: "l"(p),
                    "f"(v[0]), "f"(v[1]), "f"(v[2]), "f"(v[3]),
                    "f"(v[4]), "f"(v[5]), "f"(v[6]), "f"(v[7])
                 : "memory");
}

// One float8 (32B) per thread. 67,108,864 floats -> 8,388,608 float8
// -> 32768 blocks of 256 threads. All accesses 32B-aligned, 1KB/warp.
__global__ void __launch_bounds__(256) scatter_main_kernel(
    const float* __restrict__ in,
    const float* __restrict__ g,
    float* __restrict__ out)
{
    unsigned i8 = blockIdx.x * 256u + threadIdx.x;   // < 2^23

    unsigned w8 = i8 & 63u;           // float8 column: w = w8*8
    unsigned h  = (i8 >> 6) & 511u;
    unsigned c  = (i8 >> 15) & 63u;
    unsigned b  = i8 >> 21;

    unsigned slot = (b << 10) | ((h >> 4) << 5) | (w8 >> 1);

    float v[8];
    ldg256(in + ((size_t)i8 << 3), v);

    int p = g_head[slot];
    if (p >= 0) {
        // patch offset in float8 units: p*2048 + c*32 + (h&15)*2 + (w8&1)
        unsigned local8 = (c << 5) | ((h & 15u) << 1) | (w8 & 1u);
        do {
            float gv[8];
            ldg256(g + (((size_t)((unsigned)p << 11) + local8) << 3), gv);
            #pragma unroll
            for (int j = 0; j < 8; j++) v[j] += gv[j];
            p = g_next[p];
        } while (p >= 0);
    }

    stg256(out + ((size_t)i8 << 3), v);
}

extern "C" void kernel_launch(void* const* d_in, const int* in_sizes, int n_in,
                              void* d_out, int out_size) {
    const float* input    = (const float*)d_in[0];
    const float* gathered = (const float*)d_in[1];
    const void*  indices  = d_in[2];
    float* out = (float*)d_out;

    init_heads_kernel<<<NSLOTS / 256, 256>>>();
    build_lists_kernel<<<NN / 256, 256>>>(indices);

    const unsigned total8 = (unsigned)(BB * CC * HH * WW) / 8u;  // 8,388,608
    scatter_main_kernel<<<total8 / 256, 256>>>(input, gathered, out);
}